// round 10
// baseline (speedup 1.0000x reference)
#include <cuda_runtime.h>
#include <cuda_fp16.h>

// VNL loss, fp16 two-plane packed gather + replicated-global-REDG histogram.
// k_pack:    transpose (b,pixel) fp32 maps into two fp16 planes (16B/pixel).
//            Thread = (map, pixel): 8 coalesced LDG.32 + one dense STG.128.
// k_compute: one thread per group g; 6 LDG.128 gathers fetch all 8 batches
//            into registers; math in fp32. Per masked item ONE 64-bit global
//            atomicAdd (no return -> REDG) of ((round(L*128)<<22)|1) into
//            d_rep[replica][bin], replica = (block*8+warp)&63 (warp-uniform)
//            -> hot-bin L2 serialization divided by 64. No smem, no barriers.
// k_reduce:  16 blocks x 128 threads; thread owns one bin, folds 64 replicas
//            (coalesced) into d_hist64[bin] and re-zeros the replicas.
// k_resolve: one 1024-thread block; 2 bins/thread, block scan, rank-owner
//            resolves the quartile bin by bin-mean, re-zeros d_hist64
//            (device globals are zero at module load -> replay invariant).

#define Wd 640
#define Hd 480
#define Bn 8
#define Gn 368640            // int(8*480*640*0.15)
#define NPIX (Hd * Wd)       // 307200
#define NB 2048
#define NREP 64
#define LMAXF 3.47f          // L <= 2*sqrt(3) ~ 3.4641
#define BIN_SCALE ((float)NB / LMAXF)
#define FIXSCALE 128.0f      // per-item quantization, unbiased rn
#define INV_FIXSCALE (1.0 / 128.0)
#define CNT_MASK 0x3FFFFFull // low 22 bits = count

__device__ unsigned long long d_rep[NREP * NB];  // zero-init at module load
__device__ unsigned long long d_hist64[NB];
__device__ __half d_pack[2 * NPIX * 8];          // [plane][pixel][batch0..7]

__global__ void __launch_bounds__(256) k_pack(
    const float* __restrict__ gt, const float* __restrict__ pr)
{
    const int t = blockIdx.x * blockDim.x + threadIdx.x;   // < 2*NPIX
    const int sel = (t >= NPIX) ? 1 : 0;                   // warp-uniform (NPIX%32==0)
    const int p = t - sel * NPIX;
    const float* src = sel ? pr : gt;

    __half h[8];
    #pragma unroll
    for (int b = 0; b < Bn; b++) h[b] = __float2half(src[b * NPIX + p]);
    *(uint4*)(d_pack + (size_t)t * 8) = *(const uint4*)h;
}

__global__ void __launch_bounds__(256) k_compute(
    const int* __restrict__ p1x, const int* __restrict__ p1y,
    const int* __restrict__ p2x, const int* __restrict__ p2y,
    const int* __restrict__ p3x, const int* __restrict__ p3y)
{
    const int g = blockIdx.x * blockDim.x + threadIdx.x;   // grid covers Gn exactly
    const int rep = (blockIdx.x * 8 + (threadIdx.x >> 5)) & (NREP - 1); // warp-uniform
    unsigned long long* hrow = d_rep + (size_t)rep * NB;

    const int x1 = p1x[g], y1 = p1y[g];
    const int x2 = p2x[g], y2 = p2y[g];
    const int x3 = p3x[g], y3 = p3y[g];

    const float ax1 = ((float)x1 - 320.0f) * (1.0f / 519.0f);
    const float ay1 = ((float)y1 - 240.0f) * (1.0f / 519.0f);
    const float ax2 = ((float)x2 - 320.0f) * (1.0f / 519.0f);
    const float ay2 = ((float)y2 - 240.0f) * (1.0f / 519.0f);
    const float ax3 = ((float)x3 - 320.0f) * (1.0f / 519.0f);
    const float ay3 = ((float)y3 - 240.0f) * (1.0f / 519.0f);

    const int o1 = y1 * Wd + x1;
    const int o2 = y2 * Wd + x2;
    const int o3 = y3 * Wd + x3;

    // 6 independent 16B gathers -> all 8 batches resident; convert to fp32
    float G1[8], Q1[8], G2[8], Q2[8], G3[8], Q3[8];
    {
        uint4 a;
        __half h[8];
        a = *(const uint4*)(d_pack + (size_t)o1 * 8);
        *(uint4*)h = a;
        #pragma unroll
        for (int b = 0; b < 8; b++) G1[b] = __half2float(h[b]);
        a = *(const uint4*)(d_pack + (size_t)(NPIX + o1) * 8);
        *(uint4*)h = a;
        #pragma unroll
        for (int b = 0; b < 8; b++) Q1[b] = __half2float(h[b]);
        a = *(const uint4*)(d_pack + (size_t)o2 * 8);
        *(uint4*)h = a;
        #pragma unroll
        for (int b = 0; b < 8; b++) G2[b] = __half2float(h[b]);
        a = *(const uint4*)(d_pack + (size_t)(NPIX + o2) * 8);
        *(uint4*)h = a;
        #pragma unroll
        for (int b = 0; b < 8; b++) Q2[b] = __half2float(h[b]);
        a = *(const uint4*)(d_pack + (size_t)o3 * 8);
        *(uint4*)h = a;
        #pragma unroll
        for (int b = 0; b < 8; b++) G3[b] = __half2float(h[b]);
        a = *(const uint4*)(d_pack + (size_t)(NPIX + o3) * 8);
        *(uint4*)h = a;
        #pragma unroll
        for (int b = 0; b < 8; b++) Q3[b] = __half2float(h[b]);
    }

    #pragma unroll
    for (int b = 0; b < Bn; b++) {
        const float gd1 = G1[b], gd2 = G2[b], gd3 = G3[b];
        const float qd1 = Q1[b], qd2 = Q2[b], qd3 = Q3[b];

        // ---- GT points & diffs ----
        const float g1x = ax1 * fabsf(gd1), g1y = ay1 * fabsf(gd1), g1z = gd1;
        const float g2x = ax2 * fabsf(gd2), g2y = ay2 * fabsf(gd2), g2z = gd2;
        const float g3x = ax3 * fabsf(gd3), g3y = ay3 * fabsf(gd3), g3z = gd3;

        const float d12x = g2x - g1x, d12y = g2y - g1y, d12z = g2z - g1z;
        const float d13x = g3x - g1x, d13y = g3y - g1y, d13z = g3z - g1z;
        const float d23x = g3x - g2x, d23y = g3y - g2y, d23z = g3z - g2z;

        const float e11 = d12x*d12x + d12y*d12y + d12z*d12z;
        const float e22 = d13x*d13x + d13y*d13y + d13z*d13z;
        const float e33 = d23x*d23x + d23y*d23y + d23z*d23z;
        const float e12 = d12x*d13x + d12y*d13y + d12z*d13z;
        const float e13 = d12x*d23x + d12y*d23y + d12z*d23z;
        const float e23 = d13x*d23x + d13y*d23y + d13z*d23z;

        const float n1 = sqrtf(e11), n2 = sqrtf(e22), n3 = sqrtf(e33);
        const float DC = 0.867f, EPS = 1e-8f;
        // |e_ij| > DC*(n_i*n_j + 1e-8)  <=>  |cos_ij| > DC
        int cnt = (fabsf(e11) > DC * (n1 * n1 + EPS))
                + (fabsf(e22) > DC * (n2 * n2 + EPS))
                + (fabsf(e33) > DC * (n3 * n3 + EPS))
                + 2 * ((fabsf(e12) > DC * (n1 * n2 + EPS))
                     + (fabsf(e13) > DC * (n1 * n3 + EPS))
                     + (fabsf(e23) > DC * (n2 * n3 + EPS)));
        const bool mcos = cnt > 3;
        const bool mx = (fabsf(d12x) < 0.01f) || (fabsf(d13x) < 0.01f) || (fabsf(d23x) < 0.01f);
        const bool my = (fabsf(d12y) < 0.01f) || (fabsf(d13y) < 0.01f) || (fabsf(d23y) < 0.01f);
        const bool mz = (fabsf(d12z) < 0.01f) || (fabsf(d13z) < 0.01f) || (fabsf(d23z) < 0.01f);
        const bool mask = !((mx && my && mz) || mcos);

        // ---- Pred points (reference's zmask broadcast bug replicated:
        //      z of point c == 0  =>  coordinate c of ALL points := 1e-4) ----
        float q1x = ax1 * fabsf(qd1), q1y = ay1 * fabsf(qd1), q1z = qd1;
        float q2x = ax2 * fabsf(qd2), q2y = ay2 * fabsf(qd2), q2z = qd2;
        float q3x = ax3 * fabsf(qd3), q3y = ay3 * fabsf(qd3), q3z = qd3;
        if (qd1 == 0.0f) { q1x = 1e-4f; q2x = 1e-4f; q3x = 1e-4f; }
        if (qd2 == 0.0f) { q1y = 1e-4f; q2y = 1e-4f; q3y = 1e-4f; }
        if (qd3 == 0.0f) { q1z = 1e-4f; q2z = 1e-4f; q3z = 1e-4f; }

        const float t12x = q2x - q1x, t12y = q2y - q1y, t12z = q2z - q1z;
        const float t13x = q3x - q1x, t13y = q3y - q1y, t13z = q3z - q1z;

        // ---- normals + L1 diff of unit normals ----
        const float gnx = d12y * d13z - d12z * d13y;
        const float gny = d12z * d13x - d12x * d13z;
        const float gnz = d12x * d13y - d12y * d13x;
        const float tnx = t12y * t13z - t12z * t13y;
        const float tny = t12z * t13x - t12x * t13z;
        const float tnz = t12x * t13y - t12y * t13x;

        const float gq = gnx * gnx + gny * gny + gnz * gnz;
        const float tq = tnx * tnx + tny * tny + tnz * tnz;
        const float gi = (gq == 0.0f) ? 100.0f : rsqrtf(gq);   // norm==0 -> norm:=0.01
        const float ti = (tq == 0.0f) ? 100.0f : rsqrtf(tq);

        const float L = fabsf(gnx * gi - tnx * ti)
                      + fabsf(gny * gi - tny * ti)
                      + fabsf(gnz * gi - tnz * ti);

        if (mask) {
            int bin = (int)(L * BIN_SCALE);
            bin = bin < 0 ? 0 : (bin > NB - 1 ? NB - 1 : bin);
            // per-cell count < 2^22 (worst hot bin 2.9M/64=46K); sum << 2^42
            const unsigned long long v =
                ((unsigned long long)__float2uint_rn(L * FIXSCALE) << 22) | 1ull;
            atomicAdd(&hrow[bin], v);   // no return use -> REDG at L2
        }
    }
}

// Fold 64 replicas per bin into d_hist64, re-zero replicas. 16 x 128 threads.
__global__ void __launch_bounds__(128) k_reduce() {
    const int bin = blockIdx.x * blockDim.x + threadIdx.x;  // 0..2047
    unsigned long long acc = 0ull;
    #pragma unroll 8
    for (int r = 0; r < NREP; r++) {
        const size_t idx = (size_t)r * NB + bin;
        acc += d_rep[idx];
        d_rep[idx] = 0ull;
    }
    d_hist64[bin] = acc;
}

// One 1024-thread block resolves the trimmed mean, then re-zeros the histogram.
__global__ void __launch_bounds__(1024) k_resolve(float* out) {
    const int tid  = threadIdx.x;          // 0..1023
    const int lane = tid & 31;
    const int wid  = tid >> 5;             // 0..31

    // each thread owns bins 2*tid, 2*tid+1 (loaded once, kept in registers)
    const unsigned long long v0 = d_hist64[2 * tid];
    const unsigned long long v1 = d_hist64[2 * tid + 1];
    const int c0 = (int)(v0 & CNT_MASK), c1 = (int)(v1 & CNT_MASK);
    const double s0 = (double)(v0 >> 22) * INV_FIXSCALE;
    const double s1 = (double)(v1 >> 22) * INV_FIXSCALE;
    const int    lc = c0 + c1;
    const double ls = s0 + s1;

    // warp inclusive scans
    int ic = lc;
    double is = ls;
    #pragma unroll
    for (int o = 1; o < 32; o <<= 1) {
        int    vi = __shfl_up_sync(0xFFFFFFFFu, ic, o);
        double vd = __shfl_up_sync(0xFFFFFFFFu, is, o);
        if (lane >= o) { ic += vi; is += vd; }
    }

    __shared__ int    wc[32];
    __shared__ double ws[32];
    if (lane == 31) { wc[wid] = ic; ws[wid] = is; }
    __syncthreads();

    // warp 0 scans the 32 warp totals
    if (wid == 0) {
        int    a = wc[lane];
        double d = ws[lane];
        #pragma unroll
        for (int o = 1; o < 32; o <<= 1) {
            int    vi = __shfl_up_sync(0xFFFFFFFFu, a, o);
            double vd = __shfl_up_sync(0xFFFFFFFFu, d, o);
            if (lane >= o) { a += vi; d += vd; }
        }
        wc[lane] = a; ws[lane] = d;
    }
    __syncthreads();

    const int    wofc = (wid == 0) ? 0 : wc[wid - 1];
    const double wofs = (wid == 0) ? 0.0 : ws[wid - 1];
    ic += wofc;                  // block-inclusive prefix for this thread
    is += wofs;

    const int    n     = wc[31];
    const double total = ws[31];
    const int    drop  = n >> 2;

    const int    ec = ic - lc;   // exclusive prefixes
    const double es = is - ls;

    if (drop == 0) {
        if (tid == 0) {
            int denom = n; if (denom < 1) denom = 1;
            out[0] = (float)(total / (double)denom);
        }
    } else if (drop > ec && drop <= ic) {
        // exactly one thread owns rank 'drop'; resolve within its 2 bins
        double ds = es;
        int cum = ec;
        if (cum + c0 >= drop) {
            const int r = drop - cum;
            if (c0 > 0) ds += (double)r * (s0 / (double)c0);
        } else {
            cum += c0;
            ds += s0;
            const int r = drop - cum;
            if (c1 > 0) ds += (double)r * (s1 / (double)c1);
        }
        int denom = n - drop; if (denom < 1) denom = 1;
        out[0] = (float)((total - ds) / (double)denom);
    }

    // re-zero for the next replay
    d_hist64[2 * tid] = 0ull;
    d_hist64[2 * tid + 1] = 0ull;
}

extern "C" void kernel_launch(void* const* d_in, const int* in_sizes, int n_in,
                              void* d_out, int out_size) {
    const float* gt  = (const float*)d_in[0];
    const float* pr  = (const float*)d_in[1];
    const int*   p1x = (const int*)d_in[2];
    const int*   p1y = (const int*)d_in[3];
    const int*   p2x = (const int*)d_in[4];
    const int*   p2y = (const int*)d_in[5];
    const int*   p3x = (const int*)d_in[6];
    const int*   p3y = (const int*)d_in[7];

    k_pack<<<2 * NPIX / 256, 256>>>(gt, pr);
    k_compute<<<Gn / 256, 256>>>(p1x, p1y, p2x, p2y, p3x, p3y);
    k_reduce<<<NB / 128, 128>>>();
    k_resolve<<<1, 1024>>>((float*)d_out);
}

// round 11
// speedup vs baseline: 1.0655x; 1.0655x over previous
#include <cuda_runtime.h>
#include <cuda_fp16.h>

// VNL loss, fp16 two-plane packed gather + smem-histogram, fused tail.
// k_pack:    transpose (b,pixel) fp32 maps into two fp16 planes (16B/pixel).
//            Thread = (map, pixel): 8 coalesced LDG.32 + one dense STG.128.
// k_compute: one thread per group g; 6 LDG.128 gathers fetch all 8 batches
//            into registers; math in fp32. Per masked item one 32-bit shared
//            atomic ((round(L*128)<<12)|1) into a 1024-bin histogram; block
//            flushes nonzero bins with one 64-bit global atomic. Then the
//            LAST block (global counter) resolves the trimmed mean inline,
//            writes the scalar, and re-zeros histogram + counter so the next
//            graph replay starts clean (globals zero at module load).

#define Wd 640
#define Hd 480
#define Bn 8
#define Gn 368640            // int(8*480*640*0.15)
#define NPIX (Hd * Wd)       // 307200
#define NB 1024
#define NBLK (Gn / 256)      // 1440 compute blocks
#define LMAXF 3.47f          // L <= 2*sqrt(3) ~ 3.4641
#define BIN_SCALE ((float)NB / LMAXF)
#define FIXSCALE 128.0f      // per-item quantization, unbiased rn
#define INV_FIXSCALE (1.0 / 128.0)
#define SH_CNT_MASK 0xFFFu   // low 12 bits of shared word = count (max 2048/block)
#define CNT_MASK 0x3FFFFFull // low 22 bits of global word = count (max 2.9M)

__device__ unsigned long long d_hist64[NB];   // zero-init at module load
__device__ unsigned int d_ctr;                // zero-init at module load
__device__ __half d_pack[2 * NPIX * 8];       // [plane][pixel][batch0..7]

__global__ void __launch_bounds__(256) k_pack(
    const float* __restrict__ gt, const float* __restrict__ pr)
{
    const int t = blockIdx.x * blockDim.x + threadIdx.x;   // < 2*NPIX
    const int sel = (t >= NPIX) ? 1 : 0;                   // warp-uniform (NPIX%32==0)
    const int p = t - sel * NPIX;
    const float* src = sel ? pr : gt;

    __half h[8];
    #pragma unroll
    for (int b = 0; b < Bn; b++) h[b] = __float2half(src[b * NPIX + p]);
    *(uint4*)(d_pack + (size_t)t * 8) = *(const uint4*)h;
}

__global__ void __launch_bounds__(256) k_compute(
    const int* __restrict__ p1x, const int* __restrict__ p1y,
    const int* __restrict__ p2x, const int* __restrict__ p2y,
    const int* __restrict__ p3x, const int* __restrict__ p3y,
    float* __restrict__ out)
{
    __shared__ unsigned int sh[NB];
    __shared__ unsigned int sh_last;
    __shared__ int    wcs[8];
    __shared__ double wss[8];
    for (int j = threadIdx.x; j < NB; j += blockDim.x) sh[j] = 0u;
    __syncthreads();

    const int g = blockIdx.x * blockDim.x + threadIdx.x;   // grid covers Gn exactly

    const int x1 = p1x[g], y1 = p1y[g];
    const int x2 = p2x[g], y2 = p2y[g];
    const int x3 = p3x[g], y3 = p3y[g];

    const float ax1 = ((float)x1 - 320.0f) * (1.0f / 519.0f);
    const float ay1 = ((float)y1 - 240.0f) * (1.0f / 519.0f);
    const float ax2 = ((float)x2 - 320.0f) * (1.0f / 519.0f);
    const float ay2 = ((float)y2 - 240.0f) * (1.0f / 519.0f);
    const float ax3 = ((float)x3 - 320.0f) * (1.0f / 519.0f);
    const float ay3 = ((float)y3 - 240.0f) * (1.0f / 519.0f);

    const int o1 = y1 * Wd + x1;
    const int o2 = y2 * Wd + x2;
    const int o3 = y3 * Wd + x3;

    // 6 independent 16B gathers -> all 8 batches resident; convert to fp32
    float G1[8], Q1[8], G2[8], Q2[8], G3[8], Q3[8];
    {
        uint4 a;
        __half h[8];
        a = *(const uint4*)(d_pack + (size_t)o1 * 8);
        *(uint4*)h = a;
        #pragma unroll
        for (int b = 0; b < 8; b++) G1[b] = __half2float(h[b]);
        a = *(const uint4*)(d_pack + (size_t)(NPIX + o1) * 8);
        *(uint4*)h = a;
        #pragma unroll
        for (int b = 0; b < 8; b++) Q1[b] = __half2float(h[b]);
        a = *(const uint4*)(d_pack + (size_t)o2 * 8);
        *(uint4*)h = a;
        #pragma unroll
        for (int b = 0; b < 8; b++) G2[b] = __half2float(h[b]);
        a = *(const uint4*)(d_pack + (size_t)(NPIX + o2) * 8);
        *(uint4*)h = a;
        #pragma unroll
        for (int b = 0; b < 8; b++) Q2[b] = __half2float(h[b]);
        a = *(const uint4*)(d_pack + (size_t)o3 * 8);
        *(uint4*)h = a;
        #pragma unroll
        for (int b = 0; b < 8; b++) G3[b] = __half2float(h[b]);
        a = *(const uint4*)(d_pack + (size_t)(NPIX + o3) * 8);
        *(uint4*)h = a;
        #pragma unroll
        for (int b = 0; b < 8; b++) Q3[b] = __half2float(h[b]);
    }

    #pragma unroll
    for (int b = 0; b < Bn; b++) {
        const float gd1 = G1[b], gd2 = G2[b], gd3 = G3[b];
        const float qd1 = Q1[b], qd2 = Q2[b], qd3 = Q3[b];

        // ---- GT points & diffs ----
        const float g1x = ax1 * fabsf(gd1), g1y = ay1 * fabsf(gd1), g1z = gd1;
        const float g2x = ax2 * fabsf(gd2), g2y = ay2 * fabsf(gd2), g2z = gd2;
        const float g3x = ax3 * fabsf(gd3), g3y = ay3 * fabsf(gd3), g3z = gd3;

        const float d12x = g2x - g1x, d12y = g2y - g1y, d12z = g2z - g1z;
        const float d13x = g3x - g1x, d13y = g3y - g1y, d13z = g3z - g1z;
        const float d23x = g3x - g2x, d23y = g3y - g2y, d23z = g3z - g2z;

        const float e11 = d12x*d12x + d12y*d12y + d12z*d12z;
        const float e22 = d13x*d13x + d13y*d13y + d13z*d13z;
        const float e33 = d23x*d23x + d23y*d23y + d23z*d23z;
        const float e12 = d12x*d13x + d12y*d13y + d12z*d13z;
        const float e13 = d12x*d23x + d12y*d23y + d12z*d23z;
        const float e23 = d13x*d23x + d13y*d23y + d13z*d23z;

        const float n1 = sqrtf(e11), n2 = sqrtf(e22), n3 = sqrtf(e33);
        const float DC = 0.867f, EPS = 1e-8f;
        // |e_ij| > DC*(n_i*n_j + 1e-8)  <=>  |cos_ij| > DC
        int cnt = (fabsf(e11) > DC * (n1 * n1 + EPS))
                + (fabsf(e22) > DC * (n2 * n2 + EPS))
                + (fabsf(e33) > DC * (n3 * n3 + EPS))
                + 2 * ((fabsf(e12) > DC * (n1 * n2 + EPS))
                     + (fabsf(e13) > DC * (n1 * n3 + EPS))
                     + (fabsf(e23) > DC * (n2 * n3 + EPS)));
        const bool mcos = cnt > 3;
        const bool mx = (fabsf(d12x) < 0.01f) || (fabsf(d13x) < 0.01f) || (fabsf(d23x) < 0.01f);
        const bool my = (fabsf(d12y) < 0.01f) || (fabsf(d13y) < 0.01f) || (fabsf(d23y) < 0.01f);
        const bool mz = (fabsf(d12z) < 0.01f) || (fabsf(d13z) < 0.01f) || (fabsf(d23z) < 0.01f);
        const bool mask = !((mx && my && mz) || mcos);

        // ---- Pred points (reference's zmask broadcast bug replicated:
        //      z of point c == 0  =>  coordinate c of ALL points := 1e-4) ----
        float q1x = ax1 * fabsf(qd1), q1y = ay1 * fabsf(qd1), q1z = qd1;
        float q2x = ax2 * fabsf(qd2), q2y = ay2 * fabsf(qd2), q2z = qd2;
        float q3x = ax3 * fabsf(qd3), q3y = ay3 * fabsf(qd3), q3z = qd3;
        if (qd1 == 0.0f) { q1x = 1e-4f; q2x = 1e-4f; q3x = 1e-4f; }
        if (qd2 == 0.0f) { q1y = 1e-4f; q2y = 1e-4f; q3y = 1e-4f; }
        if (qd3 == 0.0f) { q1z = 1e-4f; q2z = 1e-4f; q3z = 1e-4f; }

        const float t12x = q2x - q1x, t12y = q2y - q1y, t12z = q2z - q1z;
        const float t13x = q3x - q1x, t13y = q3y - q1y, t13z = q3z - q1z;

        // ---- normals + L1 diff of unit normals ----
        const float gnx = d12y * d13z - d12z * d13y;
        const float gny = d12z * d13x - d12x * d13z;
        const float gnz = d12x * d13y - d12y * d13x;
        const float tnx = t12y * t13z - t12z * t13y;
        const float tny = t12z * t13x - t12x * t13z;
        const float tnz = t12x * t13y - t12y * t13x;

        const float gq = gnx * gnx + gny * gny + gnz * gnz;
        const float tq = tnx * tnx + tny * tny + tnz * tnz;
        const float gi = (gq == 0.0f) ? 100.0f : rsqrtf(gq);   // norm==0 -> norm:=0.01
        const float ti = (tq == 0.0f) ? 100.0f : rsqrtf(tq);

        const float L = fabsf(gnx * gi - tnx * ti)
                      + fabsf(gny * gi - tny * ti)
                      + fabsf(gnz * gi - tnz * ti);

        if (mask) {
            int bin = (int)(L * BIN_SCALE);
            bin = bin < 0 ? 0 : (bin > NB - 1 ? NB - 1 : bin);
            // sum field [12:32) max 2048*444 = 909312 < 2^20; count [0:12) max 2048
            const unsigned int v = (__float2uint_rn(L * FIXSCALE) << 12) | 1u;
            atomicAdd(&sh[bin], v);
        }
    }

    __syncthreads();
    for (int j = threadIdx.x; j < NB; j += blockDim.x) {
        const unsigned int v = sh[j];
        if (v) {
            const unsigned long long gv =
                ((unsigned long long)(v >> 12) << 22) | (unsigned long long)(v & SH_CNT_MASK);
            atomicAdd(&d_hist64[j], gv);
        }
    }

    // ---- last-block-done: the final block resolves the trimmed mean ----
    __threadfence();
    __syncthreads();
    if (threadIdx.x == 0) {
        const unsigned int old = atomicAdd(&d_ctr, 1u);
        sh_last = (old == NBLK - 1) ? 1u : 0u;
    }
    __syncthreads();
    if (!sh_last) return;

    // 256 threads, 4 bins each. Atomics bypassed L1, so plain loads see L2.
    const int tid  = threadIdx.x;
    const int lane = tid & 31;
    const int wid  = tid >> 5;             // 0..7

    unsigned long long v4[4];
    int    c4[4];
    double s4[4];
    int    lc = 0;
    double ls = 0.0;
    #pragma unroll
    for (int i = 0; i < 4; i++) {
        v4[i] = d_hist64[tid * 4 + i];
        c4[i] = (int)(v4[i] & CNT_MASK);
        s4[i] = (double)(v4[i] >> 22) * INV_FIXSCALE;
        lc += c4[i];
        ls += s4[i];
    }

    // warp inclusive scans
    int ic = lc;
    double is = ls;
    #pragma unroll
    for (int o = 1; o < 32; o <<= 1) {
        int    vi = __shfl_up_sync(0xFFFFFFFFu, ic, o);
        double vd = __shfl_up_sync(0xFFFFFFFFu, is, o);
        if (lane >= o) { ic += vi; is += vd; }
    }
    if (lane == 31) { wcs[wid] = ic; wss[wid] = is; }
    __syncthreads();

    if (wid == 0) {
        int    a = (lane < 8) ? wcs[lane] : 0;
        double d = (lane < 8) ? wss[lane] : 0.0;
        #pragma unroll
        for (int o = 1; o < 8; o <<= 1) {
            int    vi = __shfl_up_sync(0xFFFFFFFFu, a, o);
            double vd = __shfl_up_sync(0xFFFFFFFFu, d, o);
            if (lane >= o) { a += vi; d += vd; }
        }
        if (lane < 8) { wcs[lane] = a; wss[lane] = d; }
    }
    __syncthreads();

    const int    wofc = (wid == 0) ? 0 : wcs[wid - 1];
    const double wofs = (wid == 0) ? 0.0 : wss[wid - 1];
    ic += wofc;                  // block-inclusive prefix for this thread
    is += wofs;

    const int    n     = wcs[7];
    const double total = wss[7];
    const int    drop  = n >> 2;

    const int    ec = ic - lc;   // exclusive prefixes
    const double es = is - ls;

    if (drop == 0) {
        if (tid == 0) {
            int denom = n; if (denom < 1) denom = 1;
            out[0] = (float)(total / (double)denom);
        }
    } else if (drop > ec && drop <= ic) {
        // exactly one thread owns rank 'drop'; resolve within its 4 bins
        double ds = es;
        int cum = ec;
        #pragma unroll
        for (int i = 0; i < 4; i++) {
            if (cum + c4[i] >= drop) {
                const int r = drop - cum;
                if (c4[i] > 0) ds += (double)r * (s4[i] / (double)c4[i]);
                break;
            }
            cum += c4[i];
            ds += s4[i];
        }
        int denom = n - drop; if (denom < 1) denom = 1;
        out[0] = (float)((total - ds) / (double)denom);
    }

    // re-zero histogram + counter for the next replay
    #pragma unroll
    for (int i = 0; i < 4; i++) d_hist64[tid * 4 + i] = 0ull;
    if (tid == 0) d_ctr = 0u;
}

extern "C" void kernel_launch(void* const* d_in, const int* in_sizes, int n_in,
                              void* d_out, int out_size) {
    const float* gt  = (const float*)d_in[0];
    const float* pr  = (const float*)d_in[1];
    const int*   p1x = (const int*)d_in[2];
    const int*   p1y = (const int*)d_in[3];
    const int*   p2x = (const int*)d_in[4];
    const int*   p2y = (const int*)d_in[5];
    const int*   p3x = (const int*)d_in[6];
    const int*   p3y = (const int*)d_in[7];

    k_pack<<<2 * NPIX / 256, 256>>>(gt, pr);
    k_compute<<<NBLK, 256>>>(p1x, p1y, p2x, p2y, p3x, p3y, (float*)d_out);
}

// round 12
// speedup vs baseline: 1.2196x; 1.1446x over previous
#include <cuda_runtime.h>
#include <cuda_fp16.h>

// VNL loss, fp16 two-plane packed gather + count-only cell histogram, fused tail.
// k_pack:    transpose (b,pixel) fp32 maps into two fp16 planes (16B/pixel).
// k_compute: one thread per group g; 6 LDG.128 gathers keep all 8 batches as
//            __half2 registers (24 regs); fp32 math per item, no sqrts (diag
//            tests vs constant, offdiag via squared compare). Quantize
//            u = round(L*128) (cell = bin -> selection exact on quantized
//            values); one 32-bit shared count atomic per masked item; block
//            flushes nonzero cells; LAST block resolves the trimmed mean with
//            integer-exact scan and re-zeros state (globals zero at load).

#define Wd 640
#define Hd 480
#define Bn 8
#define Gn 368640            // int(8*480*640*0.15)
#define NPIX (Hd * Wd)       // 307200
#define NB 512               // quantization cells; u <= 443 used
#define NBLK (Gn / 256)      // 1440 compute blocks
#define FIXSCALE 128.0f
#define INV_FIXSCALE (1.0 / 128.0)

__device__ unsigned int d_hist[NB];   // zero-init at module load
__device__ unsigned int d_ctr;       // zero-init at module load
__device__ __half d_pack[2 * NPIX * 8];  // [plane][pixel][batch0..7]

__global__ void __launch_bounds__(256) k_pack(
    const float* __restrict__ gt, const float* __restrict__ pr)
{
    const int t = blockIdx.x * blockDim.x + threadIdx.x;   // < 2*NPIX
    const int sel = (t >= NPIX) ? 1 : 0;                   // warp-uniform (NPIX%32==0)
    const int p = t - sel * NPIX;
    const float* src = sel ? pr : gt;

    __half h[8];
    #pragma unroll
    for (int b = 0; b < Bn; b++) h[b] = __float2half(src[b * NPIX + p]);
    *(uint4*)(d_pack + (size_t)t * 8) = *(const uint4*)h;
}

__global__ void __launch_bounds__(256, 4) k_compute(
    const int* __restrict__ p1x, const int* __restrict__ p1y,
    const int* __restrict__ p2x, const int* __restrict__ p2y,
    const int* __restrict__ p3x, const int* __restrict__ p3y,
    float* __restrict__ out)
{
    __shared__ unsigned int sh[NB];
    __shared__ unsigned int sh_last;
    __shared__ int                wcs[8];
    __shared__ unsigned long long wss[8];
    for (int j = threadIdx.x; j < NB; j += blockDim.x) sh[j] = 0u;
    __syncthreads();

    const int g = blockIdx.x * blockDim.x + threadIdx.x;   // grid covers Gn exactly

    const int x1 = p1x[g], y1 = p1y[g];
    const int x2 = p2x[g], y2 = p2y[g];
    const int x3 = p3x[g], y3 = p3y[g];

    const float ax1 = ((float)x1 - 320.0f) * (1.0f / 519.0f);
    const float ay1 = ((float)y1 - 240.0f) * (1.0f / 519.0f);
    const float ax2 = ((float)x2 - 320.0f) * (1.0f / 519.0f);
    const float ay2 = ((float)y2 - 240.0f) * (1.0f / 519.0f);
    const float ax3 = ((float)x3 - 320.0f) * (1.0f / 519.0f);
    const float ay3 = ((float)y3 - 240.0f) * (1.0f / 519.0f);

    const int o1 = y1 * Wd + x1;
    const int o2 = y2 * Wd + x2;
    const int o3 = y3 * Wd + x3;

    // 6 independent 16B gathers; keep as __half2 registers (4 per record)
    __half2 H1[4], P1[4], H2[4], P2[4], H3[4], P3[4];
    *(uint4*)H1 = *(const uint4*)(d_pack + (size_t)o1 * 8);
    *(uint4*)P1 = *(const uint4*)(d_pack + (size_t)(NPIX + o1) * 8);
    *(uint4*)H2 = *(const uint4*)(d_pack + (size_t)o2 * 8);
    *(uint4*)P2 = *(const uint4*)(d_pack + (size_t)(NPIX + o2) * 8);
    *(uint4*)H3 = *(const uint4*)(d_pack + (size_t)o3 * 8);
    *(uint4*)P3 = *(const uint4*)(d_pack + (size_t)(NPIX + o3) * 8);

    #pragma unroll
    for (int b = 0; b < Bn; b++) {
        const int hi = b >> 1;
        const float gd1 = (b & 1) ? __high2float(H1[hi]) : __low2float(H1[hi]);
        const float gd2 = (b & 1) ? __high2float(H2[hi]) : __low2float(H2[hi]);
        const float gd3 = (b & 1) ? __high2float(H3[hi]) : __low2float(H3[hi]);
        const float qd1 = (b & 1) ? __high2float(P1[hi]) : __low2float(P1[hi]);
        const float qd2 = (b & 1) ? __high2float(P2[hi]) : __low2float(P2[hi]);
        const float qd3 = (b & 1) ? __high2float(P3[hi]) : __low2float(P3[hi]);

        // ---- GT points & diffs ----
        const float g1x = ax1 * fabsf(gd1), g1y = ay1 * fabsf(gd1), g1z = gd1;
        const float g2x = ax2 * fabsf(gd2), g2y = ay2 * fabsf(gd2), g2z = gd2;
        const float g3x = ax3 * fabsf(gd3), g3y = ay3 * fabsf(gd3), g3z = gd3;

        const float d12x = g2x - g1x, d12y = g2y - g1y, d12z = g2z - g1z;
        const float d13x = g3x - g1x, d13y = g3y - g1y, d13z = g3z - g1z;
        const float d23x = g3x - g2x, d23y = g3y - g2y, d23z = g3z - g2z;

        const float e11 = d12x*d12x + d12y*d12y + d12z*d12z;
        const float e22 = d13x*d13x + d13y*d13y + d13z*d13z;
        const float e33 = d23x*d23x + d23y*d23y + d23z*d23z;
        const float e12 = d12x*d13x + d12y*d13y + d12z*d13z;
        const float e13 = d12x*d23x + d12y*d23y + d12z*d23z;
        const float e23 = d13x*d23x + d13y*d23y + d13z*d23z;

        // diag: |e|/(e+eps) > DC  <=>  e > DC*eps/(1-DC) = 6.518e-8
        // offdiag: |e_ij| > DC*(n_i*n_j+eps)  ~  e_ij^2 > DC^2*e_ii*e_jj
        const float DTH = 6.518e-8f, DCsq = 0.751689f;
        int cnt = (e11 > DTH) + (e22 > DTH) + (e33 > DTH)
                + 2 * ((e12 * e12 > DCsq * (e11 * e22))
                     + (e13 * e13 > DCsq * (e11 * e33))
                     + (e23 * e23 > DCsq * (e22 * e33)));
        const bool mcos = cnt > 3;
        const bool mx = (fabsf(d12x) < 0.01f) || (fabsf(d13x) < 0.01f) || (fabsf(d23x) < 0.01f);
        const bool my = (fabsf(d12y) < 0.01f) || (fabsf(d13y) < 0.01f) || (fabsf(d23y) < 0.01f);
        const bool mz = (fabsf(d12z) < 0.01f) || (fabsf(d13z) < 0.01f) || (fabsf(d23z) < 0.01f);
        const bool mask = !((mx && my && mz) || mcos);

        // ---- Pred points (reference's zmask broadcast bug replicated:
        //      z of point c == 0  =>  coordinate c of ALL points := 1e-4) ----
        float q1x = ax1 * fabsf(qd1), q1y = ay1 * fabsf(qd1), q1z = qd1;
        float q2x = ax2 * fabsf(qd2), q2y = ay2 * fabsf(qd2), q2z = qd2;
        float q3x = ax3 * fabsf(qd3), q3y = ay3 * fabsf(qd3), q3z = qd3;
        if (qd1 == 0.0f) { q1x = 1e-4f; q2x = 1e-4f; q3x = 1e-4f; }
        if (qd2 == 0.0f) { q1y = 1e-4f; q2y = 1e-4f; q3y = 1e-4f; }
        if (qd3 == 0.0f) { q1z = 1e-4f; q2z = 1e-4f; q3z = 1e-4f; }

        const float t12x = q2x - q1x, t12y = q2y - q1y, t12z = q2z - q1z;
        const float t13x = q3x - q1x, t13y = q3y - q1y, t13z = q3z - q1z;

        // ---- normals + L1 diff of unit normals ----
        const float gnx = d12y * d13z - d12z * d13y;
        const float gny = d12z * d13x - d12x * d13z;
        const float gnz = d12x * d13y - d12y * d13x;
        const float tnx = t12y * t13z - t12z * t13y;
        const float tny = t12z * t13x - t12x * t13z;
        const float tnz = t12x * t13y - t12y * t13x;

        const float gq = gnx * gnx + gny * gny + gnz * gnz;
        const float tq = tnx * tnx + tny * tny + tnz * tnz;
        const float gi = (gq == 0.0f) ? 100.0f : rsqrtf(gq);   // norm==0 -> norm:=0.01
        const float ti = (tq == 0.0f) ? 100.0f : rsqrtf(tq);

        const float L = fabsf(gnx * gi - tnx * ti)
                      + fabsf(gny * gi - tny * ti)
                      + fabsf(gnz * gi - tnz * ti);

        if (mask) {
            unsigned int u = __float2uint_rn(L * FIXSCALE);
            u = u > NB - 1 ? NB - 1 : u;
            atomicAdd(&sh[u], 1u);
        }
    }

    __syncthreads();
    for (int j = threadIdx.x; j < NB; j += blockDim.x) {
        const unsigned int v = sh[j];
        if (v) atomicAdd(&d_hist[j], v);
    }

    // ---- last-block-done: the final block resolves the trimmed mean ----
    __threadfence();
    __syncthreads();
    if (threadIdx.x == 0) {
        const unsigned int old = atomicAdd(&d_ctr, 1u);
        sh_last = (old == NBLK - 1) ? 1u : 0u;
    }
    __syncthreads();
    if (!sh_last) return;

    // 256 threads, 2 cells each. Integer-exact selection on quantized values.
    const int tid  = threadIdx.x;
    const int lane = tid & 31;
    const int wid  = tid >> 5;             // 0..7

    const int b0 = tid * 2, b1 = tid * 2 + 1;
    const int c0 = (int)d_hist[b0];
    const int c1 = (int)d_hist[b1];
    const unsigned long long s0 = (unsigned long long)b0 * (unsigned int)c0;
    const unsigned long long s1 = (unsigned long long)b1 * (unsigned int)c1;
    const int                lc = c0 + c1;
    const unsigned long long ls = s0 + s1;

    // warp inclusive scans
    int ic = lc;
    unsigned long long is = ls;
    #pragma unroll
    for (int o = 1; o < 32; o <<= 1) {
        int                vi = __shfl_up_sync(0xFFFFFFFFu, ic, o);
        unsigned long long vs = __shfl_up_sync(0xFFFFFFFFu, is, o);
        if (lane >= o) { ic += vi; is += vs; }
    }
    if (lane == 31) { wcs[wid] = ic; wss[wid] = is; }
    __syncthreads();

    if (wid == 0) {
        int                a = (lane < 8) ? wcs[lane] : 0;
        unsigned long long d = (lane < 8) ? wss[lane] : 0ull;
        #pragma unroll
        for (int o = 1; o < 8; o <<= 1) {
            int                vi = __shfl_up_sync(0xFFFFFFFFu, a, o);
            unsigned long long vs = __shfl_up_sync(0xFFFFFFFFu, d, o);
            if (lane >= o) { a += vi; d += vs; }
        }
        if (lane < 8) { wcs[lane] = a; wss[lane] = d; }
    }
    __syncthreads();

    const int                wofc = (wid == 0) ? 0 : wcs[wid - 1];
    const unsigned long long wofs = (wid == 0) ? 0ull : wss[wid - 1];
    ic += wofc;
    is += wofs;

    const int                n     = wcs[7];
    const unsigned long long total = wss[7];
    const int                drop  = n >> 2;

    const int                ec = ic - lc;
    const unsigned long long es = is - ls;

    if (drop == 0) {
        if (tid == 0) {
            int denom = n; if (denom < 1) denom = 1;
            out[0] = (float)((double)total * INV_FIXSCALE / (double)denom);
        }
    } else if (drop > ec && drop <= ic) {
        // exactly one thread owns rank 'drop'; exact within its 2 cells
        unsigned long long ds = es;
        if (ec + c0 >= drop) {
            ds += (unsigned long long)(drop - ec) * (unsigned int)b0;
        } else {
            ds += s0 + (unsigned long long)(drop - ec - c0) * (unsigned int)b1;
        }
        int denom = n - drop; if (denom < 1) denom = 1;
        out[0] = (float)((double)(total - ds) * INV_FIXSCALE / (double)denom);
    }

    // re-zero histogram + counter for the next replay
    d_hist[b0] = 0u;
    d_hist[b1] = 0u;
    if (tid == 0) d_ctr = 0u;
}

extern "C" void kernel_launch(void* const* d_in, const int* in_sizes, int n_in,
                              void* d_out, int out_size) {
    const float* gt  = (const float*)d_in[0];
    const float* pr  = (const float*)d_in[1];
    const int*   p1x = (const int*)d_in[2];
    const int*   p1y = (const int*)d_in[3];
    const int*   p2x = (const int*)d_in[4];
    const int*   p2y = (const int*)d_in[5];
    const int*   p3x = (const int*)d_in[6];
    const int*   p3y = (const int*)d_in[7];

    k_pack<<<2 * NPIX / 256, 256>>>(gt, pr);
    k_compute<<<NBLK, 256>>>(p1x, p1y, p2x, p2y, p3x, p3y, (float*)d_out);
}

// round 13
// speedup vs baseline: 1.2887x; 1.0566x over previous
#include <cuda_runtime.h>
#include <cuda_fp16.h>

// VNL loss, fp16 two-plane packed gather + replicated-REDG count histogram,
// fused last-block tail.
// k_pack:    transpose (b,pixel) fp32 maps into two fp16 planes (16B/pixel).
// k_compute: one thread per group g; 6 LDG.128 gathers keep all 8 batches as
//            __half2 registers; fp32 math, no sqrts. Quantize u=round(L*128)
//            (cell = bin -> selection exact on quantized values). Per masked
//            item ONE 32-bit global atomicAdd (no return -> REDG) into
//            d_rep[replica*512+u], replica=(block*8+warp)&31 -> hot-cell L2
//            serialization /32, replica stride 2KB spreads L2 slices.
//            No smem histogram, no flush. LAST block (global counter) folds
//            the 32 replicas, resolves the trimmed mean with integer-exact
//            scan, writes the scalar, re-zeros d_rep + counter (globals are
//            zero at module load -> replay invariant).

#define Wd 640
#define Hd 480
#define Bn 8
#define Gn 368640            // int(8*480*640*0.15)
#define NPIX (Hd * Wd)       // 307200
#define NB 512               // quantization cells; u <= 443 used
#define NREP 32
#define NBLK (Gn / 256)      // 1440 compute blocks
#define FIXSCALE 128.0f
#define INV_FIXSCALE (1.0 / 128.0)

__device__ unsigned int d_rep[NREP * NB];   // zero-init at module load
__device__ unsigned int d_ctr;              // zero-init at module load
__device__ __half d_pack[2 * NPIX * 8];     // [plane][pixel][batch0..7]

__global__ void __launch_bounds__(256) k_pack(
    const float* __restrict__ gt, const float* __restrict__ pr)
{
    const int t = blockIdx.x * blockDim.x + threadIdx.x;   // < 2*NPIX
    const int sel = (t >= NPIX) ? 1 : 0;                   // warp-uniform (NPIX%32==0)
    const int p = t - sel * NPIX;
    const float* src = sel ? pr : gt;

    __half h[8];
    #pragma unroll
    for (int b = 0; b < Bn; b++) h[b] = __float2half(src[b * NPIX + p]);
    *(uint4*)(d_pack + (size_t)t * 8) = *(const uint4*)h;
}

__global__ void __launch_bounds__(256, 4) k_compute(
    const int* __restrict__ p1x, const int* __restrict__ p1y,
    const int* __restrict__ p2x, const int* __restrict__ p2y,
    const int* __restrict__ p3x, const int* __restrict__ p3y,
    float* __restrict__ out)
{
    __shared__ unsigned int sh_last;
    __shared__ int                wcs[8];
    __shared__ unsigned long long wss[8];

    const int g = blockIdx.x * blockDim.x + threadIdx.x;   // grid covers Gn exactly
    const int rep = (blockIdx.x * 8 + (threadIdx.x >> 5)) & (NREP - 1); // warp-uniform
    unsigned int* hrow = d_rep + rep * NB;

    const int x1 = p1x[g], y1 = p1y[g];
    const int x2 = p2x[g], y2 = p2y[g];
    const int x3 = p3x[g], y3 = p3y[g];

    const float ax1 = ((float)x1 - 320.0f) * (1.0f / 519.0f);
    const float ay1 = ((float)y1 - 240.0f) * (1.0f / 519.0f);
    const float ax2 = ((float)x2 - 320.0f) * (1.0f / 519.0f);
    const float ay2 = ((float)y2 - 240.0f) * (1.0f / 519.0f);
    const float ax3 = ((float)x3 - 320.0f) * (1.0f / 519.0f);
    const float ay3 = ((float)y3 - 240.0f) * (1.0f / 519.0f);

    const int o1 = y1 * Wd + x1;
    const int o2 = y2 * Wd + x2;
    const int o3 = y3 * Wd + x3;

    // 6 independent 16B gathers; keep as __half2 registers (4 per record)
    __half2 H1[4], P1[4], H2[4], P2[4], H3[4], P3[4];
    *(uint4*)H1 = *(const uint4*)(d_pack + (size_t)o1 * 8);
    *(uint4*)P1 = *(const uint4*)(d_pack + (size_t)(NPIX + o1) * 8);
    *(uint4*)H2 = *(const uint4*)(d_pack + (size_t)o2 * 8);
    *(uint4*)P2 = *(const uint4*)(d_pack + (size_t)(NPIX + o2) * 8);
    *(uint4*)H3 = *(const uint4*)(d_pack + (size_t)o3 * 8);
    *(uint4*)P3 = *(const uint4*)(d_pack + (size_t)(NPIX + o3) * 8);

    #pragma unroll
    for (int b = 0; b < Bn; b++) {
        const int hi = b >> 1;
        const float gd1 = (b & 1) ? __high2float(H1[hi]) : __low2float(H1[hi]);
        const float gd2 = (b & 1) ? __high2float(H2[hi]) : __low2float(H2[hi]);
        const float gd3 = (b & 1) ? __high2float(H3[hi]) : __low2float(H3[hi]);
        const float qd1 = (b & 1) ? __high2float(P1[hi]) : __low2float(P1[hi]);
        const float qd2 = (b & 1) ? __high2float(P2[hi]) : __low2float(P2[hi]);
        const float qd3 = (b & 1) ? __high2float(P3[hi]) : __low2float(P3[hi]);

        // ---- GT points & diffs ----
        const float g1x = ax1 * fabsf(gd1), g1y = ay1 * fabsf(gd1), g1z = gd1;
        const float g2x = ax2 * fabsf(gd2), g2y = ay2 * fabsf(gd2), g2z = gd2;
        const float g3x = ax3 * fabsf(gd3), g3y = ay3 * fabsf(gd3), g3z = gd3;

        const float d12x = g2x - g1x, d12y = g2y - g1y, d12z = g2z - g1z;
        const float d13x = g3x - g1x, d13y = g3y - g1y, d13z = g3z - g1z;
        const float d23x = g3x - g2x, d23y = g3y - g2y, d23z = g3z - g2z;

        const float e11 = d12x*d12x + d12y*d12y + d12z*d12z;
        const float e22 = d13x*d13x + d13y*d13y + d13z*d13z;
        const float e33 = d23x*d23x + d23y*d23y + d23z*d23z;
        const float e12 = d12x*d13x + d12y*d13y + d12z*d13z;
        const float e13 = d12x*d23x + d12y*d23y + d12z*d23z;
        const float e23 = d13x*d23x + d13y*d23y + d13z*d23z;

        // diag: |e|/(e+eps) > DC  <=>  e > DC*eps/(1-DC) = 6.518e-8
        // offdiag: |e_ij| > DC*(n_i*n_j+eps)  ~  e_ij^2 > DC^2*e_ii*e_jj
        const float DTH = 6.518e-8f, DCsq = 0.751689f;
        int cnt = (e11 > DTH) + (e22 > DTH) + (e33 > DTH)
                + 2 * ((e12 * e12 > DCsq * (e11 * e22))
                     + (e13 * e13 > DCsq * (e11 * e33))
                     + (e23 * e23 > DCsq * (e22 * e33)));
        const bool mcos = cnt > 3;
        const bool mx = (fabsf(d12x) < 0.01f) || (fabsf(d13x) < 0.01f) || (fabsf(d23x) < 0.01f);
        const bool my = (fabsf(d12y) < 0.01f) || (fabsf(d13y) < 0.01f) || (fabsf(d23y) < 0.01f);
        const bool mz = (fabsf(d12z) < 0.01f) || (fabsf(d13z) < 0.01f) || (fabsf(d23z) < 0.01f);
        const bool mask = !((mx && my && mz) || mcos);

        // ---- Pred points (reference's zmask broadcast bug replicated:
        //      z of point c == 0  =>  coordinate c of ALL points := 1e-4) ----
        float q1x = ax1 * fabsf(qd1), q1y = ay1 * fabsf(qd1), q1z = qd1;
        float q2x = ax2 * fabsf(qd2), q2y = ay2 * fabsf(qd2), q2z = qd2;
        float q3x = ax3 * fabsf(qd3), q3y = ay3 * fabsf(qd3), q3z = qd3;
        if (qd1 == 0.0f) { q1x = 1e-4f; q2x = 1e-4f; q3x = 1e-4f; }
        if (qd2 == 0.0f) { q1y = 1e-4f; q2y = 1e-4f; q3y = 1e-4f; }
        if (qd3 == 0.0f) { q1z = 1e-4f; q2z = 1e-4f; q3z = 1e-4f; }

        const float t12x = q2x - q1x, t12y = q2y - q1y, t12z = q2z - q1z;
        const float t13x = q3x - q1x, t13y = q3y - q1y, t13z = q3z - q1z;

        // ---- normals + L1 diff of unit normals ----
        const float gnx = d12y * d13z - d12z * d13y;
        const float gny = d12z * d13x - d12x * d13z;
        const float gnz = d12x * d13y - d12y * d13x;
        const float tnx = t12y * t13z - t12z * t13y;
        const float tny = t12z * t13x - t12x * t13z;
        const float tnz = t12x * t13y - t12y * t13x;

        const float gq = gnx * gnx + gny * gny + gnz * gnz;
        const float tq = tnx * tnx + tny * tny + tnz * tnz;
        const float gi = (gq == 0.0f) ? 100.0f : rsqrtf(gq);   // norm==0 -> norm:=0.01
        const float ti = (tq == 0.0f) ? 100.0f : rsqrtf(tq);

        const float L = fabsf(gnx * gi - tnx * ti)
                      + fabsf(gny * gi - tny * ti)
                      + fabsf(gnz * gi - tnz * ti);

        if (mask) {
            unsigned int u = __float2uint_rn(L * FIXSCALE);
            u = u > NB - 1 ? NB - 1 : u;
            atomicAdd(&hrow[u], 1u);   // no return use -> REDG at L2
        }
    }

    // ---- last-block-done: the final block folds replicas + resolves ----
    __threadfence();
    __syncthreads();
    if (threadIdx.x == 0) {
        const unsigned int old = atomicAdd(&d_ctr, 1u);
        sh_last = (old == NBLK - 1) ? 1u : 0u;
    }
    __syncthreads();
    if (!sh_last) return;

    // 256 threads, 2 cells each: fold 32 replicas (stride-NB loads, full MLP),
    // then integer-exact selection on quantized values.
    const int tid  = threadIdx.x;
    const int lane = tid & 31;
    const int wid  = tid >> 5;             // 0..7

    const int b0 = tid * 2, b1 = tid * 2 + 1;
    int c0 = 0, c1 = 0;
    #pragma unroll
    for (int r = 0; r < NREP; r++) {
        c0 += (int)d_rep[r * NB + b0];
        c1 += (int)d_rep[r * NB + b1];
    }
    #pragma unroll
    for (int r = 0; r < NREP; r++) {
        d_rep[r * NB + b0] = 0u;
        d_rep[r * NB + b1] = 0u;
    }

    const unsigned long long s0 = (unsigned long long)b0 * (unsigned int)c0;
    const unsigned long long s1 = (unsigned long long)b1 * (unsigned int)c1;
    const int                lc = c0 + c1;
    const unsigned long long ls = s0 + s1;

    // warp inclusive scans
    int ic = lc;
    unsigned long long is = ls;
    #pragma unroll
    for (int o = 1; o < 32; o <<= 1) {
        int                vi = __shfl_up_sync(0xFFFFFFFFu, ic, o);
        unsigned long long vs = __shfl_up_sync(0xFFFFFFFFu, is, o);
        if (lane >= o) { ic += vi; is += vs; }
    }
    if (lane == 31) { wcs[wid] = ic; wss[wid] = is; }
    __syncthreads();

    if (wid == 0) {
        int                a = (lane < 8) ? wcs[lane] : 0;
        unsigned long long d = (lane < 8) ? wss[lane] : 0ull;
        #pragma unroll
        for (int o = 1; o < 8; o <<= 1) {
            int                vi = __shfl_up_sync(0xFFFFFFFFu, a, o);
            unsigned long long vs = __shfl_up_sync(0xFFFFFFFFu, d, o);
            if (lane >= o) { a += vi; d += vs; }
        }
        if (lane < 8) { wcs[lane] = a; wss[lane] = d; }
    }
    __syncthreads();

    const int                wofc = (wid == 0) ? 0 : wcs[wid - 1];
    const unsigned long long wofs = (wid == 0) ? 0ull : wss[wid - 1];
    ic += wofc;
    is += wofs;

    const int                n     = wcs[7];
    const unsigned long long total = wss[7];
    const int                drop  = n >> 2;

    const int                ec = ic - lc;
    const unsigned long long es = is - ls;

    if (drop == 0) {
        if (tid == 0) {
            int denom = n; if (denom < 1) denom = 1;
            out[0] = (float)((double)total * INV_FIXSCALE / (double)denom);
        }
    } else if (drop > ec && drop <= ic) {
        // exactly one thread owns rank 'drop'; exact within its 2 cells
        unsigned long long ds = es;
        if (ec + c0 >= drop) {
            ds += (unsigned long long)(drop - ec) * (unsigned int)b0;
        } else {
            ds += s0 + (unsigned long long)(drop - ec - c0) * (unsigned int)b1;
        }
        int denom = n - drop; if (denom < 1) denom = 1;
        out[0] = (float)((double)(total - ds) * INV_FIXSCALE / (double)denom);
    }

    if (tid == 0) d_ctr = 0u;
}

extern "C" void kernel_launch(void* const* d_in, const int* in_sizes, int n_in,
                              void* d_out, int out_size) {
    const float* gt  = (const float*)d_in[0];
    const float* pr  = (const float*)d_in[1];
    const int*   p1x = (const int*)d_in[2];
    const int*   p1y = (const int*)d_in[3];
    const int*   p2x = (const int*)d_in[4];
    const int*   p2y = (const int*)d_in[5];
    const int*   p3x = (const int*)d_in[6];
    const int*   p3y = (const int*)d_in[7];

    k_pack<<<2 * NPIX / 256, 256>>>(gt, pr);
    k_compute<<<NBLK, 256>>>(p1x, p1y, p2x, p2y, p3x, p3y, (float*)d_out);
}

// round 14
// speedup vs baseline: 1.3854x; 1.0751x over previous
#include <cuda_runtime.h>
#include <cuda_fp16.h>

// VNL loss, fp16 two-plane packed gather + replicated-REDG count histogram,
// fused last-block tail. R14: occupancy 4->5 blocks/SM, fminf mask trim.
// k_pack:    transpose (b,pixel) fp32 maps into two fp16 planes (16B/pixel).
// k_compute: one thread per group g; 6 LDG.128 gathers keep all 8 batches as
//            __half2 registers; fp32 math, no sqrts. Quantize u=round(L*128)
//            (cell = bin -> selection exact on quantized values). Per masked
//            item ONE 32-bit global atomicAdd (no return -> REDG) into
//            d_rep[replica*512+u], replica=(block*8+warp)&31. LAST block
//            folds the 32 replicas, resolves the trimmed mean with
//            integer-exact scan, re-zeros state (globals zero at load).

#define Wd 640
#define Hd 480
#define Bn 8
#define Gn 368640            // int(8*480*640*0.15)
#define NPIX (Hd * Wd)       // 307200
#define NB 512               // quantization cells; u <= 443 used
#define NREP 32
#define NBLK (Gn / 256)      // 1440 compute blocks
#define FIXSCALE 128.0f
#define INV_FIXSCALE (1.0 / 128.0)

__device__ unsigned int d_rep[NREP * NB];   // zero-init at module load
__device__ unsigned int d_ctr;              // zero-init at module load
__device__ __half d_pack[2 * NPIX * 8];     // [plane][pixel][batch0..7]

__global__ void __launch_bounds__(256) k_pack(
    const float* __restrict__ gt, const float* __restrict__ pr)
{
    const int t = blockIdx.x * blockDim.x + threadIdx.x;   // < 2*NPIX
    const int sel = (t >= NPIX) ? 1 : 0;                   // warp-uniform (NPIX%32==0)
    const int p = t - sel * NPIX;
    const float* src = sel ? pr : gt;

    __half h[8];
    #pragma unroll
    for (int b = 0; b < Bn; b++) h[b] = __float2half(src[b * NPIX + p]);
    *(uint4*)(d_pack + (size_t)t * 8) = *(const uint4*)h;
}

__global__ void __launch_bounds__(256, 5) k_compute(
    const int* __restrict__ p1x, const int* __restrict__ p1y,
    const int* __restrict__ p2x, const int* __restrict__ p2y,
    const int* __restrict__ p3x, const int* __restrict__ p3y,
    float* __restrict__ out)
{
    __shared__ unsigned int sh_last;
    __shared__ int                wcs[8];
    __shared__ unsigned long long wss[8];

    const int g = blockIdx.x * blockDim.x + threadIdx.x;   // grid covers Gn exactly
    const int rep = (blockIdx.x * 8 + (threadIdx.x >> 5)) & (NREP - 1); // warp-uniform
    unsigned int* hrow = d_rep + rep * NB;

    const int x1 = p1x[g], y1 = p1y[g];
    const int x2 = p2x[g], y2 = p2y[g];
    const int x3 = p3x[g], y3 = p3y[g];

    const float ax1 = ((float)x1 - 320.0f) * (1.0f / 519.0f);
    const float ay1 = ((float)y1 - 240.0f) * (1.0f / 519.0f);
    const float ax2 = ((float)x2 - 320.0f) * (1.0f / 519.0f);
    const float ay2 = ((float)y2 - 240.0f) * (1.0f / 519.0f);
    const float ax3 = ((float)x3 - 320.0f) * (1.0f / 519.0f);
    const float ay3 = ((float)y3 - 240.0f) * (1.0f / 519.0f);

    const int o1 = y1 * Wd + x1;
    const int o2 = y2 * Wd + x2;
    const int o3 = y3 * Wd + x3;

    // 6 independent 16B gathers; keep as __half2 registers (4 per record)
    __half2 H1[4], P1[4], H2[4], P2[4], H3[4], P3[4];
    *(uint4*)H1 = *(const uint4*)(d_pack + (size_t)o1 * 8);
    *(uint4*)P1 = *(const uint4*)(d_pack + (size_t)(NPIX + o1) * 8);
    *(uint4*)H2 = *(const uint4*)(d_pack + (size_t)o2 * 8);
    *(uint4*)P2 = *(const uint4*)(d_pack + (size_t)(NPIX + o2) * 8);
    *(uint4*)H3 = *(const uint4*)(d_pack + (size_t)o3 * 8);
    *(uint4*)P3 = *(const uint4*)(d_pack + (size_t)(NPIX + o3) * 8);

    #pragma unroll
    for (int b = 0; b < Bn; b++) {
        const int hi = b >> 1;
        const float gd1 = (b & 1) ? __high2float(H1[hi]) : __low2float(H1[hi]);
        const float gd2 = (b & 1) ? __high2float(H2[hi]) : __low2float(H2[hi]);
        const float gd3 = (b & 1) ? __high2float(H3[hi]) : __low2float(H3[hi]);
        const float qd1 = (b & 1) ? __high2float(P1[hi]) : __low2float(P1[hi]);
        const float qd2 = (b & 1) ? __high2float(P2[hi]) : __low2float(P2[hi]);
        const float qd3 = (b & 1) ? __high2float(P3[hi]) : __low2float(P3[hi]);

        // ---- GT points & diffs ----
        const float g1x = ax1 * fabsf(gd1), g1y = ay1 * fabsf(gd1), g1z = gd1;
        const float g2x = ax2 * fabsf(gd2), g2y = ay2 * fabsf(gd2), g2z = gd2;
        const float g3x = ax3 * fabsf(gd3), g3y = ay3 * fabsf(gd3), g3z = gd3;

        const float d12x = g2x - g1x, d12y = g2y - g1y, d12z = g2z - g1z;
        const float d13x = g3x - g1x, d13y = g3y - g1y, d13z = g3z - g1z;
        const float d23x = g3x - g2x, d23y = g3y - g2y, d23z = g3z - g2z;

        const float e11 = d12x*d12x + d12y*d12y + d12z*d12z;
        const float e22 = d13x*d13x + d13y*d13y + d13z*d13z;
        const float e33 = d23x*d23x + d23y*d23y + d23z*d23z;
        const float e12 = d12x*d13x + d12y*d13y + d12z*d13z;
        const float e13 = d12x*d23x + d12y*d23y + d12z*d23z;
        const float e23 = d13x*d23x + d13y*d23y + d13z*d23z;

        // diag: |e|/(e+eps) > DC  <=>  e > DC*eps/(1-DC) = 6.518e-8
        // offdiag: |e_ij| > DC*(n_i*n_j+eps)  ~  e_ij^2 > DC^2*e_ii*e_jj
        const float DTH = 6.518e-8f, DCsq = 0.751689f;
        int cnt = (e11 > DTH) + (e22 > DTH) + (e33 > DTH)
                + 2 * ((e12 * e12 > DCsq * (e11 * e22))
                     + (e13 * e13 > DCsq * (e11 * e33))
                     + (e23 * e23 > DCsq * (e22 * e33)));
        const bool mcos = cnt > 3;
        const bool mx = fminf(fminf(fabsf(d12x), fabsf(d13x)), fabsf(d23x)) < 0.01f;
        const bool my = fminf(fminf(fabsf(d12y), fabsf(d13y)), fabsf(d23y)) < 0.01f;
        const bool mz = fminf(fminf(fabsf(d12z), fabsf(d13z)), fabsf(d23z)) < 0.01f;
        const bool mask = !((mx && my && mz) || mcos);

        // ---- Pred points (reference's zmask broadcast bug replicated:
        //      z of point c == 0  =>  coordinate c of ALL points := 1e-4) ----
        float q1x = ax1 * fabsf(qd1), q1y = ay1 * fabsf(qd1), q1z = qd1;
        float q2x = ax2 * fabsf(qd2), q2y = ay2 * fabsf(qd2), q2z = qd2;
        float q3x = ax3 * fabsf(qd3), q3y = ay3 * fabsf(qd3), q3z = qd3;
        if (qd1 == 0.0f) { q1x = 1e-4f; q2x = 1e-4f; q3x = 1e-4f; }
        if (qd2 == 0.0f) { q1y = 1e-4f; q2y = 1e-4f; q3y = 1e-4f; }
        if (qd3 == 0.0f) { q1z = 1e-4f; q2z = 1e-4f; q3z = 1e-4f; }

        const float t12x = q2x - q1x, t12y = q2y - q1y, t12z = q2z - q1z;
        const float t13x = q3x - q1x, t13y = q3y - q1y, t13z = q3z - q1z;

        // ---- normals + L1 diff of unit normals ----
        const float gnx = d12y * d13z - d12z * d13y;
        const float gny = d12z * d13x - d12x * d13z;
        const float gnz = d12x * d13y - d12y * d13x;
        const float tnx = t12y * t13z - t12z * t13y;
        const float tny = t12z * t13x - t12x * t13z;
        const float tnz = t12x * t13y - t12y * t13x;

        const float gq = gnx * gnx + gny * gny + gnz * gnz;
        const float tq = tnx * tnx + tny * tny + tnz * tnz;
        const float gi = (gq == 0.0f) ? 100.0f : rsqrtf(gq);   // norm==0 -> norm:=0.01
        const float ti = (tq == 0.0f) ? 100.0f : rsqrtf(tq);

        const float L = fabsf(gnx * gi - tnx * ti)
                      + fabsf(gny * gi - tny * ti)
                      + fabsf(gnz * gi - tnz * ti);

        if (mask) {
            unsigned int u = __float2uint_rn(L * FIXSCALE);
            u = u > NB - 1 ? NB - 1 : u;
            atomicAdd(&hrow[u], 1u);   // no return use -> REDG at L2
        }
    }

    // ---- last-block-done: the final block folds replicas + resolves ----
    __threadfence();
    __syncthreads();
    if (threadIdx.x == 0) {
        const unsigned int old = atomicAdd(&d_ctr, 1u);
        sh_last = (old == NBLK - 1) ? 1u : 0u;
    }
    __syncthreads();
    if (!sh_last) return;

    // 256 threads, 2 cells each: fold 32 replicas (stride-NB loads, full MLP),
    // then integer-exact selection on quantized values.
    const int tid  = threadIdx.x;
    const int lane = tid & 31;
    const int wid  = tid >> 5;             // 0..7

    const int b0 = tid * 2, b1 = tid * 2 + 1;
    int c0 = 0, c1 = 0;
    #pragma unroll
    for (int r = 0; r < NREP; r++) {
        c0 += (int)d_rep[r * NB + b0];
        c1 += (int)d_rep[r * NB + b1];
    }
    #pragma unroll
    for (int r = 0; r < NREP; r++) {
        d_rep[r * NB + b0] = 0u;
        d_rep[r * NB + b1] = 0u;
    }

    const unsigned long long s0 = (unsigned long long)b0 * (unsigned int)c0;
    const unsigned long long s1 = (unsigned long long)b1 * (unsigned int)c1;
    const int                lc = c0 + c1;
    const unsigned long long ls = s0 + s1;

    // warp inclusive scans
    int ic = lc;
    unsigned long long is = ls;
    #pragma unroll
    for (int o = 1; o < 32; o <<= 1) {
        int                vi = __shfl_up_sync(0xFFFFFFFFu, ic, o);
        unsigned long long vs = __shfl_up_sync(0xFFFFFFFFu, is, o);
        if (lane >= o) { ic += vi; is += vs; }
    }
    if (lane == 31) { wcs[wid] = ic; wss[wid] = is; }
    __syncthreads();

    if (wid == 0) {
        int                a = (lane < 8) ? wcs[lane] : 0;
        unsigned long long d = (lane < 8) ? wss[lane] : 0ull;
        #pragma unroll
        for (int o = 1; o < 8; o <<= 1) {
            int                vi = __shfl_up_sync(0xFFFFFFFFu, a, o);
            unsigned long long vs = __shfl_up_sync(0xFFFFFFFFu, d, o);
            if (lane >= o) { a += vi; d += vs; }
        }
        if (lane < 8) { wcs[lane] = a; wss[lane] = d; }
    }
    __syncthreads();

    const int                wofc = (wid == 0) ? 0 : wcs[wid - 1];
    const unsigned long long wofs = (wid == 0) ? 0ull : wss[wid - 1];
    ic += wofc;
    is += wofs;

    const int                n     = wcs[7];
    const unsigned long long total = wss[7];
    const int                drop  = n >> 2;

    const int                ec = ic - lc;
    const unsigned long long es = is - ls;

    if (drop == 0) {
        if (tid == 0) {
            int denom = n; if (denom < 1) denom = 1;
            out[0] = (float)((double)total * INV_FIXSCALE / (double)denom);
        }
    } else if (drop > ec && drop <= ic) {
        // exactly one thread owns rank 'drop'; exact within its 2 cells
        unsigned long long ds = es;
        if (ec + c0 >= drop) {
            ds += (unsigned long long)(drop - ec) * (unsigned int)b0;
        } else {
            ds += s0 + (unsigned long long)(drop - ec - c0) * (unsigned int)b1;
        }
        int denom = n - drop; if (denom < 1) denom = 1;
        out[0] = (float)((double)(total - ds) * INV_FIXSCALE / (double)denom);
    }

    if (tid == 0) d_ctr = 0u;
}

extern "C" void kernel_launch(void* const* d_in, const int* in_sizes, int n_in,
                              void* d_out, int out_size) {
    const float* gt  = (const float*)d_in[0];
    const float* pr  = (const float*)d_in[1];
    const int*   p1x = (const int*)d_in[2];
    const int*   p1y = (const int*)d_in[3];
    const int*   p2x = (const int*)d_in[4];
    const int*   p2y = (const int*)d_in[5];
    const int*   p3x = (const int*)d_in[6];
    const int*   p3y = (const int*)d_in[7];

    k_pack<<<2 * NPIX / 256, 256>>>(gt, pr);
    k_compute<<<NBLK, 256>>>(p1x, p1y, p2x, p2y, p3x, p3y, (float*)d_out);
}